// round 17
// baseline (speedup 1.0000x reference)
#include <cuda_runtime.h>
#include <cuda_fp16.h>
#include <cstdint>

// ---------------------------------------------------------------------------
// GCN, fp16 inter-layer features, ONE persistent kernel for everything after
// the CSR build and GEMM:
//   branch A: memsets, place (bucket CSR; cur==degree; inline dtype detect)
//   branch B: ph_raw = half(x @ W1)
//   k_mid (persistent, 592 blocks co-resident, global spin barriers):
//     phase0: dinv=rsqrt(1+deg); ph *= dinv
//     phase1: qh[n] = half(dn*(dn*(sum ph)+b1))
//     phase2: h[n] = dn*sum qh; pool[batch[n]] += h; cnt[batch[n]] += 1
//     phase3: blocks 0..7: z = relu((pool/cnt)@W2+b2)@fcW1+fcb1), BN partials
//     phase4: block 0: batchnorm + fc2 + softplus -> out
// ---------------------------------------------------------------------------

#define MAXN 100000
#define MAXE 1600000
#define MAXG 256
#define C 32
#define CAP 64
#define MIDGRID 592

__device__ int    g_bucket[MAXN * CAP];
__device__ int    g_cur[MAXN];         // placement cursor == degree afterwards
__device__ int    g_ovf_dst[MAXE];
__device__ int    g_ovf_src[MAXE];
__device__ int    g_ovf_cnt;
__device__ float  g_dinv[MAXN];
__device__ __half g_ph[MAXN * C];      // half p (raw, then scaled in place)
__device__ __half g_qh[MAXN * C];      // half q
__device__ float  g_pool[MAXG * C];
__device__ int    g_gcnt[MAXG];        // nodes per graph
__device__ float  g_z[MAXG * 32];
__device__ float  g_bn[64];            // [0:32) sum, [32:64) sumsq
__device__ int    g_sync[4];           // barrier counters

static inline int ceil_div(int a, int b) { return (a + b - 1) / b; }

// Host-side stream/event objects (created once; host objects, no device mem)
struct StreamPack {
    cudaStream_t s2;
    cudaEvent_t ev_fork, ev_join;
    StreamPack() {
        cudaStreamCreateWithFlags(&s2, cudaStreamNonBlocking);
        cudaEventCreateWithFlags(&ev_fork, cudaEventDisableTiming);
        cudaEventCreateWithFlags(&ev_join, cudaEventDisableTiming);
    }
};
static StreamPack g_sp;

__device__ __forceinline__ int idx_get(const void* p, long i, int is64) {
    // int64 path: load only the low 32-bit word (values are < 2^31)
    return is64 ? ((const int*)p)[2 * i] : ((const int*)p)[i];
}

// Per-block dtype detection: for little-endian non-negative int64, every odd
// 32-bit word is 0. Sample 256 odd words spread over the first half of the
// buffer (safe for both widths). Warp 0 only; result in *flag after syncthreads.
__device__ __forceinline__ void detect_dtype(const unsigned* buf, long nelem_min,
                                             int* flag /*smem*/) {
    if (threadIdx.x < 32) {
        unsigned a = 0u;
        long half = nelem_min / 2;
        for (int s = 0; s < 8; s++) {
            long idx = (long)(threadIdx.x * 8 + s);
            long j = (idx * half) / 256;       // j in [0, half)
            a |= buf[2 * j + 1];
        }
#pragma unroll
        for (int o = 16; o > 0; o >>= 1) a |= __shfl_down_sync(0xFFFFFFFFu, a, o);
        if (threadIdx.x == 0) *flag = (a == 0u) ? 1 : 0;
    }
    __syncthreads();
}

// ---------------------------------------------------------------------------
// One-pass bucket placement, 4 independent edges/thread; inline edge-dtype
// detect per block; block 0 zeroes bn/sync/gcnt scratch.
// ---------------------------------------------------------------------------
__global__ void k_place(const void* __restrict__ eidx, int E) {
    __shared__ int s_is64;
    detect_dtype((const unsigned*)eidx, (long)2 * E, &s_is64);
    int is64 = s_is64;

    if (blockIdx.x == 0) {
        if (threadIdx.x < 64) g_bn[threadIdx.x] = 0.0f;
        if (threadIdx.x >= 64 && threadIdx.x < 68) g_sync[threadIdx.x - 64] = 0;
        if (threadIdx.x < MAXG) g_gcnt[threadIdx.x] = 0;
    }

    int T = gridDim.x * blockDim.x;
    int tid = blockIdx.x * blockDim.x + threadIdx.x;

    int s[4], t[4], sl[4];
    bool v[4];
#pragma unroll
    for (int u = 0; u < 4; u++) {
        int e = tid + u * T;
        v[u] = e < E;
        if (v[u]) {
            s[u] = idx_get(eidx, e, is64);
            t[u] = idx_get(eidx, (long)E + e, is64);
        }
    }
#pragma unroll
    for (int u = 0; u < 4; u++) {
        if (v[u]) sl[u] = atomicAdd(&g_cur[t[u]], 1);
    }
#pragma unroll
    for (int u = 0; u < 4; u++) {
        if (v[u]) {
            if (sl[u] < CAP) g_bucket[(size_t)t[u] * CAP + sl[u]] = s[u];
            else { int o = atomicAdd(&g_ovf_cnt, 1); g_ovf_dst[o] = t[u]; g_ovf_src[o] = s[u]; }
        }
    }
}

// ---------------------------------------------------------------------------
// GEMM raw (packed fma.rn.f32x2): ph_raw[n,:] = half(x[n,:] @ W1)
// ---------------------------------------------------------------------------
__global__ void __launch_bounds__(256) k_gemm1(const float* __restrict__ x,
                                               const float* __restrict__ W1, int N) {
    __shared__ unsigned long long sW[128 * 16];
    const unsigned long long* Wp = (const unsigned long long*)W1;
    for (int i = threadIdx.x; i < 128 * 16; i += 256) sW[i] = Wp[i];
    __syncthreads();

    int n = blockIdx.x * 256 + threadIdx.x;
    if (n >= N) return;

    unsigned long long acc[16];
#pragma unroll
    for (int j = 0; j < 16; j++) acc[j] = 0ull;

    const float4* xr = (const float4*)(x + (size_t)n * 128);
#pragma unroll 2
    for (int k4 = 0; k4 < 32; k4++) {
        float4 xv = __ldg(&xr[k4]);
        const float* xf = (const float*)&xv;
#pragma unroll
        for (int kk = 0; kk < 4; kk++) {
            unsigned xb = __float_as_uint(xf[kk]);
            unsigned long long xx;
            asm("mov.b64 %0, {%1, %1};" : "=l"(xx) : "r"(xb));
            const unsigned long long* wr = sW + (k4 * 4 + kk) * 16;
#pragma unroll
            for (int j = 0; j < 16; j++) {
                asm("fma.rn.f32x2 %0, %1, %2, %0;"
                    : "+l"(acc[j]) : "l"(xx), "l"(wr[j]));
            }
        }
    }

    unsigned hh[16];
#pragma unroll
    for (int j = 0; j < 16; j++) {
        unsigned lo, hi;
        asm("mov.b64 {%0, %1}, %2;" : "=r"(lo), "=r"(hi) : "l"(acc[j]));
        __half2 h = __floats2half2_rn(__uint_as_float(lo), __uint_as_float(hi));
        hh[j] = *(unsigned*)&h;
    }
    uint4* out = (uint4*)(g_ph + (size_t)n * C);
#pragma unroll
    for (int j = 0; j < 4; j++) {
        out[j] = make_uint4(hh[4 * j], hh[4 * j + 1], hh[4 * j + 2], hh[4 * j + 3]);
    }
}

// ---------------------------------------------------------------------------
// Gather helpers (half source): 4 threads/node, lane owns 8 halves (LDG.128),
// 32-bit address arithmetic, fp32 accumulation.
// ---------------------------------------------------------------------------
__device__ __forceinline__ void acc_h8(uint4 v, float* a) {
    const unsigned* w = (const unsigned*)&v;
#pragma unroll
    for (int k = 0; k < 4; k++) {
        __half2 h = *(__half2*)&w[k];
        float2 f = __half22float2(h);
        a[2 * k]     += f.x;
        a[2 * k + 1] += f.y;
    }
}

__device__ __forceinline__ uint4 ldg_row(const char* base, unsigned row, unsigned laneoff) {
    return __ldg((const uint4*)(base + (row << 6) + laneoff));
}

__device__ __forceinline__ void gather_sum_h(const __half* __restrict__ Fsrc,
                                             int node, int lane, float* out) {
    int deg = g_cur[node];
    int m = deg < CAP ? deg : CAP;
    const int4* bp4 = (const int4*)(g_bucket + (size_t)node * CAP);
    const char* base = (const char*)Fsrc;
    unsigned laneoff = (unsigned)lane << 4;

    float a[8], b[8];
#pragma unroll
    for (int k = 0; k < 8; k++) { a[k] = 0.0f; b[k] = 0.0f; }
    acc_h8(ldg_row(base, (unsigned)node, laneoff), a);  // self-loop

    int e = 0;
    for (; e + 4 <= m; e += 4) {
        int4 ia = __ldg(&bp4[e >> 2]);
        uint4 v0 = ldg_row(base, (unsigned)ia.x, laneoff);
        uint4 v1 = ldg_row(base, (unsigned)ia.y, laneoff);
        uint4 v2 = ldg_row(base, (unsigned)ia.z, laneoff);
        uint4 v3 = ldg_row(base, (unsigned)ia.w, laneoff);
        acc_h8(v0, a); acc_h8(v1, b); acc_h8(v2, a); acc_h8(v3, b);
    }
    const int* bp = (const int*)bp4;
    for (; e < m; e++) {
        int i0 = __ldg(&bp[e]);
        acc_h8(ldg_row(base, (unsigned)i0, laneoff), a);
    }
    if (deg > CAP) {   // exact overflow handling (normally empty)
        int oc = g_ovf_cnt;
        for (int i = 0; i < oc; i++) {
            if (g_ovf_dst[i] == node) {
                acc_h8(ldg_row(base, (unsigned)g_ovf_src[i], laneoff), a);
            }
        }
    }
#pragma unroll
    for (int k = 0; k < 8; k++) out[k] = a[k] + b[k];
}

// Global barrier: all gridDim.x blocks co-resident.
__device__ __forceinline__ void gbar(int* ctr, int target) {
    __syncthreads();
    if (threadIdx.x == 0) {
        __threadfence();
        atomicAdd(ctr, 1);
        while (*(volatile int*)ctr < target) { }
        __threadfence();
    }
    __syncthreads();
}

// ---------------------------------------------------------------------------
// Persistent kernel: scale | gather1 | gather2+pool+cnt | headA | headB
// ---------------------------------------------------------------------------
__global__ void __launch_bounds__(256, 4) k_mid(const float* __restrict__ b1,
                                                const void* __restrict__ batch,
                                                int N, int G,
                                                const float* __restrict__ W2,
                                                const float* __restrict__ b2,
                                                const float* __restrict__ fcW1,
                                                const float* __restrict__ fcb1,
                                                const float* __restrict__ gamma,
                                                const float* __restrict__ beta,
                                                const float* __restrict__ fcW2,
                                                const float* __restrict__ fcb2,
                                                float* __restrict__ out) {
    __shared__ int s_is64b;
    __shared__ float sWa[2048];   // W2 (headA) -- reused smem
    __shared__ float sWb[2048];   // fcW1 (headA)
    detect_dtype((const unsigned*)batch, (long)N, &s_is64b);
    int is64b = s_is64b;

    int grid = gridDim.x;
    int chunk = (N + grid - 1) / grid;
    int n0 = blockIdx.x * chunk;
    int n1 = n0 + chunk; if (n1 > N) n1 = N;
    if (n0 > N) n0 = N;

    // ---- phase 0: dinv + in-place scale of ph ----
    for (int i = n0 * 4 + (int)threadIdx.x; i < n1 * 4; i += 256) {
        int n = i >> 2;
        float di = rsqrtf(1.0f + (float)g_cur[n]);
        if ((i & 3) == 0) g_dinv[n] = di;
        uint4 v = ((const uint4*)g_ph)[i];
        unsigned* w = (unsigned*)&v;
#pragma unroll
        for (int k = 0; k < 4; k++) {
            __half2 h = *(__half2*)&w[k];
            float2 f = __half22float2(h);
            __half2 r = __floats2half2_rn(f.x * di, f.y * di);
            w[k] = *(unsigned*)&r;
        }
        ((uint4*)g_ph)[i] = v;
    }

    gbar(&g_sync[0], grid);

    // ---- phase 1: gather1, q = dinv*(dinv*sum + b1) -> half ----
    {
        int lane = threadIdx.x & 3;
        float4 bv0 = ((const float4*)b1)[lane * 2];
        float4 bv1 = ((const float4*)b1)[lane * 2 + 1];
        for (int base = n0; base < n1; base += 64) {
            int node = base + ((int)threadIdx.x >> 2);
            if (node < n1) {
                float acc[8];
                gather_sum_h(g_ph, node, lane, acc);
                float di = g_dinv[node];
                float q[8];
                q[0] = di * (di * acc[0] + bv0.x);
                q[1] = di * (di * acc[1] + bv0.y);
                q[2] = di * (di * acc[2] + bv0.z);
                q[3] = di * (di * acc[3] + bv0.w);
                q[4] = di * (di * acc[4] + bv1.x);
                q[5] = di * (di * acc[5] + bv1.y);
                q[6] = di * (di * acc[6] + bv1.z);
                q[7] = di * (di * acc[7] + bv1.w);
                unsigned hh[4];
#pragma unroll
                for (int k = 0; k < 4; k++) {
                    __half2 h = __floats2half2_rn(q[2 * k], q[2 * k + 1]);
                    hh[k] = *(unsigned*)&h;
                }
                ((uint4*)g_qh)[(size_t)node * 4 + lane] =
                    make_uint4(hh[0], hh[1], hh[2], hh[3]);
            }
        }
    }

    gbar(&g_sync[1], grid);

    // ---- phase 2: gather2 + pooling + per-graph counts ----
    {
        int lane = threadIdx.x & 3;
        for (int base = n0; base < n1; base += 64) {
            int node = base + ((int)threadIdx.x >> 2);
            if (node < n1) {
                float acc[8];
                gather_sum_h(g_qh, node, lane, acc);
                float di = g_dinv[node];
                int gidx = idx_get(batch, node, is64b);
                float* pp = g_pool + (size_t)gidx * C + lane * 8;
                float4 h0 = make_float4(di * acc[0], di * acc[1], di * acc[2], di * acc[3]);
                float4 h1 = make_float4(di * acc[4], di * acc[5], di * acc[6], di * acc[7]);
                asm volatile("red.global.add.v4.f32 [%0], {%1, %2, %3, %4};"
                             :: "l"(pp), "f"(h0.x), "f"(h0.y), "f"(h0.z), "f"(h0.w) : "memory");
                asm volatile("red.global.add.v4.f32 [%0], {%1, %2, %3, %4};"
                             :: "l"(pp + 4), "f"(h1.x), "f"(h1.y), "f"(h1.z), "f"(h1.w) : "memory");
                if (lane == 0) {
                    asm volatile("red.global.add.s32 [%0], %1;"
                                 :: "l"(g_gcnt + gidx), "r"(1) : "memory");
                }
            }
        }
    }

    gbar(&g_sync[2], grid);

    // ---- phase 3: headA on blocks 0..ceil(G/32)-1 (tid<128: 4 thr/graph) ----
    int nHeadBlocks = (G + 31) / 32;
    if ((int)blockIdx.x < nHeadBlocks) {
        int tid = threadIdx.x;
        for (int i = tid; i < 2048; i += 256) { sWa[i] = W2[i]; sWb[i] = fcW1[i]; }
        __syncthreads();

        if (tid < 128) {
            int gl = tid >> 2;
            int q = tid & 3;
            int g = blockIdx.x * 32 + gl;
            if (g < G) {
                int cnt = g_gcnt[g];
                float inv_cnt = 1.0f / (float)max(cnt, 1);

                float r[32];
#pragma unroll
                for (int i = 0; i < 32; i++) r[i] = g_pool[g * 32 + i] * inv_cnt;

                float o2[16];
#pragma unroll
                for (int j = 0; j < 16; j++) o2[j] = __ldg(&b2[q * 16 + j]);
                for (int k = 0; k < 32; k++) {
                    float rk = r[k];
                    const float* wrow = sWa + k * 64 + q * 16;
#pragma unroll
                    for (int j = 0; j < 16; j++) o2[j] = fmaf(rk, wrow[j], o2[j]);
                }

                float zz[32];
#pragma unroll
                for (int i = 0; i < 32; i++) zz[i] = 0.0f;
                for (int j = 0; j < 16; j++) {
                    float oj = o2[j];
                    const float* frow = sWb + (q * 16 + j) * 32;
#pragma unroll
                    for (int i = 0; i < 32; i++) zz[i] = fmaf(oj, frow[i], zz[i]);
                }

                unsigned fm = 0xFFFFFFFFu;
#pragma unroll
                for (int i = 0; i < 32; i++) {
                    zz[i] += __shfl_xor_sync(fm, zz[i], 1);
                    zz[i] += __shfl_xor_sync(fm, zz[i], 2);
                }

                float z[32];
#pragma unroll
                for (int i = 0; i < 32; i++) z[i] = fmaxf(zz[i] + __ldg(&fcb1[i]), 0.0f);
                if (q == 0) {
#pragma unroll
                    for (int i = 0; i < 32; i++) g_z[g * 32 + i] = z[i];
                }
                for (int i = 0; i < 32; i++) {
                    float v = (q == 0) ? z[i] : 0.0f;
                    float v2 = v * v;
#pragma unroll
                    for (int o = 16; o > 0; o >>= 1) {
                        v += __shfl_down_sync(fm, v, o);
                        v2 += __shfl_down_sync(fm, v2, o);
                    }
                    if ((tid & 31) == 0) {
                        atomicAdd(&g_bn[i], v);
                        atomicAdd(&g_bn[32 + i], v2);
                    }
                }
            }
        }
    }

    gbar(&g_sync[3], grid);

    // ---- phase 4: headB on block 0 ----
    if (blockIdx.x == 0) {
        __shared__ float smu[32], sis[32], sgam[32], sbet[32], sfw2[32];
        int tid = threadIdx.x;
        if (tid < 32) {
            float invG = 1.0f / (float)G;
            float mu = g_bn[tid] * invG;
            float var = g_bn[32 + tid] * invG - mu * mu;
            smu[tid] = mu;
            sis[tid] = rsqrtf(var + 1e-5f);
            sgam[tid] = gamma[tid];
            sbet[tid] = beta[tid];
            sfw2[tid] = fcW2[tid];
        }
        __syncthreads();

        float fb2 = __ldg(&fcb2[0]);
        for (int g = tid; g < G; g += 256) {
            float acc = fb2;
#pragma unroll
            for (int i = 0; i < 32; i++) {
                float zb = (g_z[g * 32 + i] - smu[i]) * sis[i] * sgam[i] + sbet[i];
                acc = fmaf(zb, sfw2[i], acc);
            }
            out[g] = fmaxf(acc, 0.0f) + log1pf(expf(-fabsf(acc)));
        }
    }
}

// ---------------------------------------------------------------------------
extern "C" void kernel_launch(void* const* d_in, const int* in_sizes, int n_in,
                              void* d_out, int out_size) {
    const float* x     = (const float*)d_in[0];
    const void*  eidx  = d_in[1];
    const void*  batch = d_in[2];
    const float* W1    = (const float*)d_in[3];
    const float* b1    = (const float*)d_in[4];
    const float* W2    = (const float*)d_in[5];
    const float* b2    = (const float*)d_in[6];
    const float* fcW1  = (const float*)d_in[7];
    const float* fcb1  = (const float*)d_in[8];
    const float* gamma = (const float*)d_in[9];
    const float* beta  = (const float*)d_in[10];
    const float* fcW2  = (const float*)d_in[11];
    const float* fcb2  = (const float*)d_in[12];

    int N = in_sizes[0] / 128;
    int E = in_sizes[1] / 2;
    int G = out_size;

    void *pcur, *ppool, *povf;
    cudaGetSymbolAddress(&pcur, g_cur);
    cudaGetSymbolAddress(&ppool, g_pool);
    cudaGetSymbolAddress(&povf, g_ovf_cnt);

    // Fork: branch B (s2) runs the GEMM, independent of the CSR build.
    cudaEventRecord(g_sp.ev_fork, 0);
    cudaStreamWaitEvent(g_sp.s2, g_sp.ev_fork, 0);
    k_gemm1<<<ceil_div(N, 256), 256, 0, g_sp.s2>>>(x, W1, N);
    cudaEventRecord(g_sp.ev_join, g_sp.s2);

    // Branch A: init + place on the default stream.
    cudaMemsetAsync(pcur, 0, (size_t)N * sizeof(int));
    cudaMemsetAsync(ppool, 0, (size_t)G * C * sizeof(float));
    cudaMemsetAsync(povf, 0, sizeof(int));
    k_place<<<ceil_div(E, 1024), 256>>>(eidx, E);

    // Join and run the fused persistent tail (everything else).
    cudaStreamWaitEvent(0, g_sp.ev_join, 0);
    k_mid<<<MIDGRID, 256>>>(b1, batch, N, G, W2, b2, fcW1, fcb1,
                            gamma, beta, fcW2, fcb2, (float*)d_out);
}